// round 11
// baseline (speedup 1.0000x reference)
#include <cuda_runtime.h>
#include <cuda_fp16.h>
#include <cstdint>

#define Bn 128
#define Nn 256
#define Dn 512
#define Hn 1024
#define Ln 3

// ---------------------------------------------------------------------------
// Scratch planes (single fp16 plane each; 16B-aligned)
// ---------------------------------------------------------------------------
__device__ __align__(256) __half g_adjh[Nn * Nn];
__device__ __align__(256) __half g_xh [(size_t)Bn * Nn * Dn];
__device__ __align__(256) __half g_nbh[(size_t)Bn * Nn * Dn];
__device__ __align__(256) __half g_hh [(size_t)Bn * Nn * Hn];
__device__ __align__(256) __half g_w1h[(size_t)Ln * Hn * Dn];
__device__ __align__(256) __half g_w2h[(size_t)Ln * Dn * Hn];
__device__ __align__(256) float  g_x  [(size_t)Bn * Nn * Dn];

// ---------------------------------------------------------------------------
// PTX helpers
// ---------------------------------------------------------------------------
__device__ __forceinline__ uint32_t smem_u32(const void* p) {
    uint32_t a;
    asm("{ .reg .u64 t; cvta.to.shared.u64 t, %1; cvt.u32.u64 %0, t; }"
        : "=r"(a) : "l"(p));
    return a;
}
__device__ __forceinline__ void cp16(uint32_t s, const void* g) {
    asm volatile("cp.async.cg.shared.global [%0], [%1], 16;" :: "r"(s), "l"(g));
}
__device__ __forceinline__ void cp_commit() {
    asm volatile("cp.async.commit_group;" ::: "memory");
}
template<int N>
__device__ __forceinline__ void cp_wait() {
    asm volatile("cp.async.wait_group %0;" :: "n"(N) : "memory");
}
__device__ __forceinline__ void ldsm_x4(uint32_t (&r)[4], uint32_t addr) {
    asm volatile("ldmatrix.sync.aligned.m8n8.x4.shared.b16 {%0,%1,%2,%3}, [%4];"
        : "=r"(r[0]), "=r"(r[1]), "=r"(r[2]), "=r"(r[3]) : "r"(addr));
}
__device__ __forceinline__ void ldsm_x4_t(uint32_t (&r)[4], uint32_t addr) {
    asm volatile("ldmatrix.sync.aligned.m8n8.x4.trans.shared.b16 {%0,%1,%2,%3}, [%4];"
        : "=r"(r[0]), "=r"(r[1]), "=r"(r[2]), "=r"(r[3]) : "r"(addr));
}
__device__ __forceinline__ void mma16816(float (&d)[4], const uint32_t (&a)[4],
                                         uint32_t b0, uint32_t b1) {
    asm volatile(
        "mma.sync.aligned.m16n8k16.row.col.f32.f16.f16.f32 "
        "{%0,%1,%2,%3}, {%4,%5,%6,%7}, {%8,%9}, {%0,%1,%2,%3};"
        : "+f"(d[0]), "+f"(d[1]), "+f"(d[2]), "+f"(d[3])
        : "r"(a[0]), "r"(a[1]), "r"(a[2]), "r"(a[3]), "r"(b0), "r"(b1));
}

// ---------------------------------------------------------------------------
// Row softmax over adjacency [N,N]: fp32 output + fp16 plane
// ---------------------------------------------------------------------------
__global__ void softmax_rows(const float* __restrict__ adj,
                             float* __restrict__ out_adj,
                             __half* __restrict__ hi)
{
    int row = blockIdx.x;
    int t   = threadIdx.x;
    float v = adj[row * Nn + t];

    __shared__ float red[8];
    float m = v;
    #pragma unroll
    for (int o = 16; o > 0; o >>= 1)
        m = fmaxf(m, __shfl_xor_sync(0xffffffffu, m, o));
    if ((t & 31) == 0) red[t >> 5] = m;
    __syncthreads();
    m = red[0];
    #pragma unroll
    for (int i = 1; i < 8; i++) m = fmaxf(m, red[i]);
    __syncthreads();

    float e = expf(v - m);
    float s = e;
    #pragma unroll
    for (int o = 16; o > 0; o >>= 1)
        s += __shfl_xor_sync(0xffffffffu, s, o);
    if ((t & 31) == 0) red[t >> 5] = s;
    __syncthreads();
    s = red[0];
    #pragma unroll
    for (int i = 1; i < 8; i++) s += red[i];

    float o = e / s;
    out_adj[row * Nn + t] = o;
    hi[row * Nn + t] = __float2half_rn(o);
}

// ---------------------------------------------------------------------------
// fp32 -> fp16 plane converters
// ---------------------------------------------------------------------------
__global__ void cvt_weights(const float* __restrict__ W1, const float* __restrict__ W2,
                            __half* __restrict__ w1h, __half* __restrict__ w2h, int n4)
{
    int idx = blockIdx.x * blockDim.x + threadIdx.x;
    if (idx >= n4) return;
    const float* in = blockIdx.y ? W2 : W1;
    __half* hi = blockIdx.y ? w2h : w1h;
    float4 v = ((const float4*)in)[idx];
    __half h0 = __float2half_rn(v.x), h1 = __float2half_rn(v.y);
    __half h2 = __float2half_rn(v.z), h3 = __float2half_rn(v.w);
    ((uint2*)hi)[idx] = make_uint2(
        (uint32_t)__half_as_ushort(h0) | ((uint32_t)__half_as_ushort(h1) << 16),
        (uint32_t)__half_as_ushort(h2) | ((uint32_t)__half_as_ushort(h3) << 16));
}

__global__ void cvt_fp16(const float* __restrict__ in, __half* __restrict__ hi, int n4)
{
    int idx = blockIdx.x * blockDim.x + threadIdx.x;
    if (idx >= n4) return;
    float4 v = ((const float4*)in)[idx];
    __half h0 = __float2half_rn(v.x), h1 = __float2half_rn(v.y);
    __half h2 = __float2half_rn(v.z), h3 = __float2half_rn(v.w);
    ((uint2*)hi)[idx] = make_uint2(
        (uint32_t)__half_as_ushort(h0) | ((uint32_t)__half_as_ushort(h1) << 16),
        (uint32_t)__half_as_ushort(h2) | ((uint32_t)__half_as_ushort(h3) << 16));
}

// ---------------------------------------------------------------------------
// Plain fp16 GEMM (fp32 accumulate): C = act(A @ op(B) + bias) (+resid)
//   A: fp16 [M,K] row-major
//   B NT: fp16 [Ncol,K] row-major (weights); B T: fp16 [K,Ncol] (x, batched z)
// CTA tile 128x128xKc64, 256 threads = 8 warps (2x4 grid), warp tile 64x32.
// 2-stage cp.async; ONE chunk = 64 k (4 ks sub-steps) between barriers.
// ---------------------------------------------------------------------------
#define PITCH    72      // halves; 144B rows (A and B-NT tiles, 128 x 64)
#define PITCH_BT 136     // halves; 272B rows (B-T tile, 64 x 128)
#define SLOT_B   18432   // bytes per operand slot: 128*72*2 (B-T: 64*136*2=17408 fits)
#define STAGE_B  (2 * SLOT_B)
#define DSMEM_B  (2 * STAGE_B)

template<bool TRANSB, bool HASBIAS, bool RELU, bool RESID, bool OUTF32, bool OUTHALF>
__global__ void __launch_bounds__(256, 2)
mma_gemm(const __half* __restrict__ Ah, const __half* __restrict__ Bh,
         const float* __restrict__ bias, const float* __restrict__ resid,
         float* __restrict__ Cf, __half* __restrict__ Ch,
         int Ncol, int K)
{
    extern __shared__ __align__(16) char dsm[];
    __shared__ float sbias[128];

    const int tid  = threadIdx.x;
    const int lane = tid & 31;
    const int wid  = tid >> 5;
    const int mwarp = (wid >> 2) * 64;   // 0 or 64
    const int nwarp = (wid & 3) * 32;    // 0,32,64,96
    const int bm = blockIdx.y * 128;
    const int bn = blockIdx.x * 128;
    const int z  = blockIdx.z;

    const size_t arow0 = (size_t)bm;
    const __half* Bhp = Bh;
    size_t out_row0;
    if (TRANSB) {
        Bhp = Bh + (size_t)z * Nn * Dn;
        out_row0 = (size_t)z * Nn + bm;
    } else {
        out_row0 = (size_t)bm;
    }

    if (HASBIAS && tid < 128) sbias[tid] = bias[bn + tid];

    float acc[4][4][4];
    #pragma unroll
    for (int mi = 0; mi < 4; mi++)
        #pragma unroll
        for (int ni = 0; ni < 4; ni++)
            #pragma unroll
            for (int e = 0; e < 4; e++) acc[mi][ni][e] = 0.f;

    const uint32_t dsm_u = smem_u32(dsm);

    // per-thread ldmatrix base offsets (byte, within a stage)
    const int q = lane >> 3, li = lane & 7;
    const uint32_t aLds = (uint32_t)(((mwarp + (q & 1) * 8 + li) * PITCH
                                     + (q >> 1) * 8) << 1);
    uint32_t bLds;
    if (TRANSB)
        bLds = (uint32_t)((((q & 1) * 8 + li) * PITCH_BT
                          + nwarp + (q >> 1) * 8) << 1);
    else
        bLds = (uint32_t)(((nwarp + (q >> 1) * 8 + li) * PITCH
                          + (q & 1) * 8) << 1);

    // issue cp.async loads for one 64-k chunk into stage s
    auto issue = [&](int k0, int s) {
        const uint32_t sa = dsm_u + (uint32_t)s * STAGE_B;
        const uint32_t sb = sa + SLOT_B;
        #pragma unroll
        for (int i = 0; i < 4; i++) {
            int f = tid + i * 256;                 // 0..1023
            int r = f >> 3, c = (f & 7) << 3;      // r: 0..127, c: 0..56
            uint32_t so = (uint32_t)((r * PITCH + c) << 1);
            cp16(sa + so, Ah + (arow0 + r) * (size_t)K + k0 + c);
            if (TRANSB) {
                int rb = f >> 4, cb = (f & 15) << 3;   // rb: 0..63, cb: 0..120
                uint32_t sob = (uint32_t)((rb * PITCH_BT + cb) << 1);
                cp16(sb + sob, Bhp + (size_t)(k0 + rb) * Ncol + bn + cb);
            } else {
                cp16(sb + so, Bhp + (size_t)(bn + r) * K + k0 + c);
            }
        }
        cp_commit();
    };

    const int nchunks = K >> 6;
    issue(0, 0);

    for (int ch = 0; ch < nchunks; ch++) {
        if (ch + 1 < nchunks) {
            issue((ch + 1) << 6, (ch + 1) & 1);
            cp_wait<1>();
        } else {
            cp_wait<0>();
        }
        __syncthreads();

        const uint32_t stg = dsm_u + (uint32_t)(ch & 1) * STAGE_B;
        const uint32_t sa  = stg + aLds;
        const uint32_t sb  = stg + SLOT_B + bLds;

        #pragma unroll
        for (int ks = 0; ks < 4; ks++) {
            uint32_t bh[2][4];
            #pragma unroll
            for (int nj = 0; nj < 2; nj++) {
                if (TRANSB) {
                    uint32_t o = (uint32_t)((ks * 16 * PITCH_BT + nj * 16) << 1);
                    ldsm_x4_t(bh[nj], sb + o);
                } else {
                    uint32_t o = (uint32_t)((nj * 16 * PITCH + ks * 16) << 1);
                    ldsm_x4(bh[nj], sb + o);
                }
            }
            uint32_t af[4][4];
            #pragma unroll
            for (int mi = 0; mi < 4; mi++)
                ldsm_x4(af[mi], sa + (uint32_t)((mi * 16 * PITCH + ks * 16) << 1));
            #pragma unroll
            for (int mi = 0; mi < 4; mi++)
                #pragma unroll
                for (int ni = 0; ni < 4; ni++) {
                    int nj = ni >> 1, p = (ni & 1) * 2;
                    mma16816(acc[mi][ni], af[mi], bh[nj][p], bh[nj][p + 1]);
                }
        }
        __syncthreads();
    }

    // ---- epilogue ----
    const int rql = lane >> 2;
    const int cql = (lane & 3) << 1;
    #pragma unroll
    for (int mi = 0; mi < 4; mi++) {
        #pragma unroll
        for (int ni = 0; ni < 4; ni++) {
            int coln = nwarp + ni * 8 + cql;
            float b0 = 0.f, b1 = 0.f;
            if (HASBIAS) { b0 = sbias[coln]; b1 = sbias[coln + 1]; }
            #pragma unroll
            for (int half = 0; half < 2; half++) {
                size_t row = out_row0 + mwarp + mi * 16 + rql + half * 8;
                float v0 = acc[mi][ni][half * 2 + 0] + b0;
                float v1 = acc[mi][ni][half * 2 + 1] + b1;
                if (RELU) { v0 = fmaxf(v0, 0.f); v1 = fmaxf(v1, 0.f); }
                size_t goff = row * (size_t)Ncol + bn + coln;
                if (RESID) {
                    float2 r = *(const float2*)(resid + goff);
                    v0 += r.x; v1 += r.y;
                }
                if (OUTF32) *(float2*)(Cf + goff) = make_float2(v0, v1);
                if (OUTHALF) {
                    __half h0 = __float2half_rn(v0), h1 = __float2half_rn(v1);
                    *(uint32_t*)(Ch + goff) =
                        (uint32_t)__half_as_ushort(h0) |
                        ((uint32_t)__half_as_ushort(h1) << 16);
                }
            }
        }
    }
}

// ---------------------------------------------------------------------------
__global__ void pool_mean(const float* __restrict__ x, float* __restrict__ pooled)
{
    int idx = blockIdx.x * blockDim.x + threadIdx.x;
    int b = idx / Dn;
    int d = idx - b * Dn;
    const float* p = x + (size_t)b * Nn * Dn + d;
    float s = 0.f;
    #pragma unroll 8
    for (int n = 0; n < Nn; n++) s += p[(size_t)n * Dn];
    pooled[idx] = s * (1.f / Nn);
}

// ---------------------------------------------------------------------------
extern "C" void kernel_launch(void* const* d_in, const int* in_sizes, int n_in,
                              void* d_out, int out_size)
{
    const float* x0  = (const float*)d_in[0];
    const float* adj = (const float*)d_in[1];
    const float* W1  = (const float*)d_in[2];
    const float* b1  = (const float*)d_in[3];
    const float* W2  = (const float*)d_in[4];
    const float* b2  = (const float*)d_in[5];

    float* out      = (float*)d_out;
    float* out_x    = out;
    float* out_pool = out + (size_t)Bn * Nn * Dn;
    float* out_adj  = out_pool + (size_t)Bn * Dn;

    __half *adjh, *xh, *nbh, *hh, *w1h, *w2h;
    float* gx;
    cudaGetSymbolAddress((void**)&adjh, g_adjh);
    cudaGetSymbolAddress((void**)&xh,   g_xh);
    cudaGetSymbolAddress((void**)&nbh,  g_nbh);
    cudaGetSymbolAddress((void**)&hh,   g_hh);
    cudaGetSymbolAddress((void**)&w1h,  g_w1h);
    cudaGetSymbolAddress((void**)&w2h,  g_w2h);
    cudaGetSymbolAddress((void**)&gx,   g_x);

    cudaFuncSetAttribute(mma_gemm<true,  false, false, false, false, true>,
        cudaFuncAttributeMaxDynamicSharedMemorySize, DSMEM_B);
    cudaFuncSetAttribute(mma_gemm<false, true,  true,  false, false, true>,
        cudaFuncAttributeMaxDynamicSharedMemorySize, DSMEM_B);
    cudaFuncSetAttribute(mma_gemm<false, true,  false, true,  true,  true>,
        cudaFuncAttributeMaxDynamicSharedMemorySize, DSMEM_B);
    cudaFuncSetAttribute(mma_gemm<false, true,  false, true,  true,  false>,
        cudaFuncAttributeMaxDynamicSharedMemorySize, DSMEM_B);

    softmax_rows<<<Nn, Nn>>>(adj, out_adj, adjh);
    cvt_weights<<<dim3(Ln * Hn * Dn / 4 / 256, 2), 256>>>(
        W1, W2, w1h, w2h, Ln * Hn * Dn / 4);
    cvt_fp16<<<((int)((size_t)Bn * Nn * Dn / 4) + 255) / 256, 256>>>(
        x0, xh, (int)((size_t)Bn * Nn * Dn / 4));

    const float* xin_f = x0;
    for (int i = 0; i < Ln; i++) {
        float* xout = (i == Ln - 1) ? out_x : gx;
        bool last = (i == Ln - 1);

        // neighbor = adj_norm @ x  (A = adj fp16; B = x fp16, T case) -> nb fp16
        mma_gemm<true, false, false, false, false, true>
            <<<dim3(Dn / 128, Nn / 128, Bn), 256, DSMEM_B>>>(
            adjh, xh, nullptr, nullptr, nullptr, nbh, Dn, Nn);

        // h = relu(nb @ W1^T + b1) -> h fp16
        mma_gemm<false, true, true, false, false, true>
            <<<dim3(Hn / 128, (Bn * Nn) / 128, 1), 256, DSMEM_B>>>(
            nbh, w1h + (size_t)i * Hn * Dn,
            b1 + (size_t)i * Hn, nullptr, nullptr, hh, Hn, Dn);

        // x = x + h @ W2^T + b2
        if (!last)
            mma_gemm<false, true, false, true, true, true>
                <<<dim3(Dn / 128, (Bn * Nn) / 128, 1), 256, DSMEM_B>>>(
                hh, w2h + (size_t)i * Dn * Hn,
                b2 + (size_t)i * Dn, xin_f, xout, xh, Dn, Hn);
        else
            mma_gemm<false, true, false, true, true, false>
                <<<dim3(Dn / 128, (Bn * Nn) / 128, 1), 256, DSMEM_B>>>(
                hh, w2h + (size_t)i * Dn * Hn,
                b2 + (size_t)i * Dn, xin_f, xout, nullptr, Dn, Hn);

        xin_f = xout;
    }

    pool_mean<<<(Bn * Dn) / 256, 256>>>(out_x, out_pool);
}

// round 12
// speedup vs baseline: 1.0562x; 1.0562x over previous
#include <cuda_runtime.h>
#include <cuda_fp16.h>
#include <cstdint>

#define Bn 128
#define Nn 256
#define Dn 512
#define Hn 1024
#define Ln 3

// ---------------------------------------------------------------------------
// Scratch planes (single fp16 plane each; 16B-aligned)
// ---------------------------------------------------------------------------
__device__ __align__(256) __half g_adjh[Nn * Nn];
__device__ __align__(256) __half g_xh [(size_t)Bn * Nn * Dn];
__device__ __align__(256) __half g_nbh[(size_t)Bn * Nn * Dn];
__device__ __align__(256) __half g_hh [(size_t)Bn * Nn * Hn];
__device__ __align__(256) __half g_w1h[(size_t)Ln * Hn * Dn];
__device__ __align__(256) __half g_w2h[(size_t)Ln * Dn * Hn];
__device__ __align__(256) float  g_x  [(size_t)Bn * Nn * Dn];

// ---------------------------------------------------------------------------
// PTX helpers
// ---------------------------------------------------------------------------
__device__ __forceinline__ uint32_t smem_u32(const void* p) {
    uint32_t a;
    asm("{ .reg .u64 t; cvta.to.shared.u64 t, %1; cvt.u32.u64 %0, t; }"
        : "=r"(a) : "l"(p));
    return a;
}
__device__ __forceinline__ void cp16(uint32_t s, const void* g) {
    asm volatile("cp.async.cg.shared.global [%0], [%1], 16;" :: "r"(s), "l"(g));
}
__device__ __forceinline__ void cp_commit() {
    asm volatile("cp.async.commit_group;" ::: "memory");
}
template<int N>
__device__ __forceinline__ void cp_wait() {
    asm volatile("cp.async.wait_group %0;" :: "n"(N) : "memory");
}
__device__ __forceinline__ void ldsm_x4(uint32_t (&r)[4], uint32_t addr) {
    asm volatile("ldmatrix.sync.aligned.m8n8.x4.shared.b16 {%0,%1,%2,%3}, [%4];"
        : "=r"(r[0]), "=r"(r[1]), "=r"(r[2]), "=r"(r[3]) : "r"(addr));
}
__device__ __forceinline__ void ldsm_x4_t(uint32_t (&r)[4], uint32_t addr) {
    asm volatile("ldmatrix.sync.aligned.m8n8.x4.trans.shared.b16 {%0,%1,%2,%3}, [%4];"
        : "=r"(r[0]), "=r"(r[1]), "=r"(r[2]), "=r"(r[3]) : "r"(addr));
}
__device__ __forceinline__ void mma16816(float (&d)[4], const uint32_t (&a)[4],
                                         uint32_t b0, uint32_t b1) {
    asm volatile(
        "mma.sync.aligned.m16n8k16.row.col.f32.f16.f16.f32 "
        "{%0,%1,%2,%3}, {%4,%5,%6,%7}, {%8,%9}, {%0,%1,%2,%3};"
        : "+f"(d[0]), "+f"(d[1]), "+f"(d[2]), "+f"(d[3])
        : "r"(a[0]), "r"(a[1]), "r"(a[2]), "r"(a[3]), "r"(b0), "r"(b1));
}

// ---------------------------------------------------------------------------
// Row softmax over adjacency [N,N]: fp32 output + fp16 plane
// ---------------------------------------------------------------------------
__global__ void softmax_rows(const float* __restrict__ adj,
                             float* __restrict__ out_adj,
                             __half* __restrict__ hi)
{
    int row = blockIdx.x;
    int t   = threadIdx.x;
    float v = adj[row * Nn + t];

    __shared__ float red[8];
    float m = v;
    #pragma unroll
    for (int o = 16; o > 0; o >>= 1)
        m = fmaxf(m, __shfl_xor_sync(0xffffffffu, m, o));
    if ((t & 31) == 0) red[t >> 5] = m;
    __syncthreads();
    m = red[0];
    #pragma unroll
    for (int i = 1; i < 8; i++) m = fmaxf(m, red[i]);
    __syncthreads();

    float e = expf(v - m);
    float s = e;
    #pragma unroll
    for (int o = 16; o > 0; o >>= 1)
        s += __shfl_xor_sync(0xffffffffu, s, o);
    if ((t & 31) == 0) red[t >> 5] = s;
    __syncthreads();
    s = red[0];
    #pragma unroll
    for (int i = 1; i < 8; i++) s += red[i];

    float o = e / s;
    out_adj[row * Nn + t] = o;
    hi[row * Nn + t] = __float2half_rn(o);
}

// ---------------------------------------------------------------------------
// fp32 -> fp16 plane converters
// ---------------------------------------------------------------------------
__global__ void cvt_weights(const float* __restrict__ W1, const float* __restrict__ W2,
                            __half* __restrict__ w1h, __half* __restrict__ w2h, int n4)
{
    int idx = blockIdx.x * blockDim.x + threadIdx.x;
    if (idx >= n4) return;
    const float* in = blockIdx.y ? W2 : W1;
    __half* hi = blockIdx.y ? w2h : w1h;
    float4 v = ((const float4*)in)[idx];
    __half h0 = __float2half_rn(v.x), h1 = __float2half_rn(v.y);
    __half h2 = __float2half_rn(v.z), h3 = __float2half_rn(v.w);
    ((uint2*)hi)[idx] = make_uint2(
        (uint32_t)__half_as_ushort(h0) | ((uint32_t)__half_as_ushort(h1) << 16),
        (uint32_t)__half_as_ushort(h2) | ((uint32_t)__half_as_ushort(h3) << 16));
}

__global__ void cvt_fp16(const float* __restrict__ in, __half* __restrict__ hi, int n4)
{
    int idx = blockIdx.x * blockDim.x + threadIdx.x;
    if (idx >= n4) return;
    float4 v = ((const float4*)in)[idx];
    __half h0 = __float2half_rn(v.x), h1 = __float2half_rn(v.y);
    __half h2 = __float2half_rn(v.z), h3 = __float2half_rn(v.w);
    ((uint2*)hi)[idx] = make_uint2(
        (uint32_t)__half_as_ushort(h0) | ((uint32_t)__half_as_ushort(h1) << 16),
        (uint32_t)__half_as_ushort(h2) | ((uint32_t)__half_as_ushort(h3) << 16));
}

// ---------------------------------------------------------------------------
// Plain fp16 GEMM (fp32 accumulate): C = act(A @ op(B) + bias) (+resid)
//   A: fp16 [M,K] row-major
//   B NT: fp16 [Ncol,K] row-major (weights); B T: fp16 [K,Ncol] (x, batched z)
// CTA tile 128x128xKc64, 128 threads (2x2 warps, warp tile 64x64).
// 2-stage cp.async; register double-buffered fragments across ks steps.
// ---------------------------------------------------------------------------
#define PITCH    72      // halves; 144B rows (A and B-NT tiles, 128 x 64)
#define PITCH_BT 136     // halves; 272B rows (B-T tile, 64 x 128)
#define SLOT_B   18432   // bytes per operand slot: 128*72*2 (B-T: 64*136*2=17408 fits)
#define STAGE_B  (2 * SLOT_B)
#define DSMEM_B  (2 * STAGE_B)

template<bool TRANSB, bool HASBIAS, bool RELU, bool RESID, bool OUTF32, bool OUTHALF>
__global__ void __launch_bounds__(128, 2)
mma_gemm(const __half* __restrict__ Ah, const __half* __restrict__ Bh,
         const float* __restrict__ bias, const float* __restrict__ resid,
         float* __restrict__ Cf, __half* __restrict__ Ch,
         int Ncol, int K)
{
    extern __shared__ __align__(16) char dsm[];
    __shared__ float sbias[128];

    const int tid  = threadIdx.x;
    const int lane = tid & 31;
    const int wid  = tid >> 5;
    const int mwarp = (wid >> 1) * 64;
    const int nwarp = (wid & 1) * 64;
    const int bm = blockIdx.y * 128;
    const int bn = blockIdx.x * 128;
    const int z  = blockIdx.z;

    const size_t arow0 = (size_t)bm;
    const __half* Bhp = Bh;
    size_t out_row0;
    if (TRANSB) {
        Bhp = Bh + (size_t)z * Nn * Dn;
        out_row0 = (size_t)z * Nn + bm;
    } else {
        out_row0 = (size_t)bm;
    }

    if (HASBIAS && tid < 128) sbias[tid] = bias[bn + tid];

    float acc[4][8][4];
    #pragma unroll
    for (int mi = 0; mi < 4; mi++)
        #pragma unroll
        for (int ni = 0; ni < 8; ni++)
            #pragma unroll
            for (int e = 0; e < 4; e++) acc[mi][ni][e] = 0.f;

    const uint32_t dsm_u = smem_u32(dsm);

    // per-thread ldmatrix base offsets (byte, within a stage)
    const int q = lane >> 3, li = lane & 7;
    const uint32_t aLds = (uint32_t)(((mwarp + (q & 1) * 8 + li) * PITCH
                                     + (q >> 1) * 8) << 1);
    uint32_t bLds;
    if (TRANSB)
        bLds = (uint32_t)((((q & 1) * 8 + li) * PITCH_BT
                          + nwarp + (q >> 1) * 8) << 1);
    else
        bLds = (uint32_t)(((nwarp + (q >> 1) * 8 + li) * PITCH
                          + (q & 1) * 8) << 1);

    // issue cp.async loads for one 64-k chunk into stage s
    auto issue = [&](int k0, int s) {
        const uint32_t sa = dsm_u + (uint32_t)s * STAGE_B;
        const uint32_t sb = sa + SLOT_B;
        #pragma unroll
        for (int i = 0; i < 8; i++) {
            int f = tid + i * 128;                 // 0..1023
            int r = f >> 3, c = (f & 7) << 3;      // r: 0..127, c: 0..56
            uint32_t so = (uint32_t)((r * PITCH + c) << 1);
            cp16(sa + so, Ah + (arow0 + r) * (size_t)K + k0 + c);
            if (TRANSB) {
                int rb = f >> 4, cb = (f & 15) << 3;   // rb: 0..63, cb: 0..120
                uint32_t sob = (uint32_t)((rb * PITCH_BT + cb) << 1);
                cp16(sb + sob, Bhp + (size_t)(k0 + rb) * Ncol + bn + cb);
            } else {
                cp16(sb + so, Bhp + (size_t)(bn + r) * K + k0 + c);
            }
        }
        cp_commit();
    };

    // fragment double buffers
    uint32_t af[2][4][4];
    uint32_t bh[2][4][4];

    const int nchunks = K >> 6;
    issue(0, 0);

    for (int ch = 0; ch < nchunks; ch++) {
        if (ch + 1 < nchunks) {
            issue((ch + 1) << 6, (ch + 1) & 1);
            cp_wait<1>();
        } else {
            cp_wait<0>();
        }
        __syncthreads();

        const uint32_t stg = dsm_u + (uint32_t)(ch & 1) * STAGE_B;
        const uint32_t sa  = stg + aLds;
        const uint32_t sb  = stg + SLOT_B + bLds;

        // load fragments for ks=0 into buffer 0
        #pragma unroll
        for (int nj = 0; nj < 4; nj++) {
            if (TRANSB) ldsm_x4_t(bh[0][nj], sb + (uint32_t)((nj * 16) << 1));
            else        ldsm_x4  (bh[0][nj], sb + (uint32_t)((nj * 16 * PITCH) << 1));
        }
        #pragma unroll
        for (int mi = 0; mi < 4; mi++)
            ldsm_x4(af[0][mi], sa + (uint32_t)((mi * 16 * PITCH) << 1));

        #pragma unroll
        for (int ks = 0; ks < 4; ks++) {
            const int cur = ks & 1;
            const int nxt = cur ^ 1;
            if (ks < 3) {
                // prefetch fragments for ks+1 into the other buffer
                #pragma unroll
                for (int nj = 0; nj < 4; nj++) {
                    if (TRANSB)
                        ldsm_x4_t(bh[nxt][nj],
                                  sb + (uint32_t)(((ks + 1) * 16 * PITCH_BT + nj * 16) << 1));
                    else
                        ldsm_x4(bh[nxt][nj],
                                sb + (uint32_t)((nj * 16 * PITCH + (ks + 1) * 16) << 1));
                }
                #pragma unroll
                for (int mi = 0; mi < 4; mi++)
                    ldsm_x4(af[nxt][mi],
                            sa + (uint32_t)((mi * 16 * PITCH + (ks + 1) * 16) << 1));
            }
            #pragma unroll
            for (int mi = 0; mi < 4; mi++)
                #pragma unroll
                for (int ni = 0; ni < 8; ni++) {
                    int nj = ni >> 1, p = (ni & 1) * 2;
                    mma16816(acc[mi][ni], af[cur][mi], bh[cur][nj][p], bh[cur][nj][p + 1]);
                }
        }
        __syncthreads();
    }

    // ---- epilogue ----
    const int rql = lane >> 2;
    const int cql = (lane & 3) << 1;
    #pragma unroll
    for (int mi = 0; mi < 4; mi++) {
        #pragma unroll
        for (int ni = 0; ni < 8; ni++) {
            int coln = nwarp + ni * 8 + cql;
            float b0 = 0.f, b1 = 0.f;
            if (HASBIAS) { b0 = sbias[coln]; b1 = sbias[coln + 1]; }
            #pragma unroll
            for (int half = 0; half < 2; half++) {
                size_t row = out_row0 + mwarp + mi * 16 + rql + half * 8;
                float v0 = acc[mi][ni][half * 2 + 0] + b0;
                float v1 = acc[mi][ni][half * 2 + 1] + b1;
                if (RELU) { v0 = fmaxf(v0, 0.f); v1 = fmaxf(v1, 0.f); }
                size_t goff = row * (size_t)Ncol + bn + coln;
                if (RESID) {
                    float2 r = *(const float2*)(resid + goff);
                    v0 += r.x; v1 += r.y;
                }
                if (OUTF32) *(float2*)(Cf + goff) = make_float2(v0, v1);
                if (OUTHALF) {
                    __half h0 = __float2half_rn(v0), h1 = __float2half_rn(v1);
                    *(uint32_t*)(Ch + goff) =
                        (uint32_t)__half_as_ushort(h0) |
                        ((uint32_t)__half_as_ushort(h1) << 16);
                }
            }
        }
    }
}

// ---------------------------------------------------------------------------
__global__ void pool_mean(const float* __restrict__ x, float* __restrict__ pooled)
{
    int idx = blockIdx.x * blockDim.x + threadIdx.x;
    int b = idx / Dn;
    int d = idx - b * Dn;
    const float* p = x + (size_t)b * Nn * Dn + d;
    float s = 0.f;
    #pragma unroll 8
    for (int n = 0; n < Nn; n++) s += p[(size_t)n * Dn];
    pooled[idx] = s * (1.f / Nn);
}

// ---------------------------------------------------------------------------
extern "C" void kernel_launch(void* const* d_in, const int* in_sizes, int n_in,
                              void* d_out, int out_size)
{
    const float* x0  = (const float*)d_in[0];
    const float* adj = (const float*)d_in[1];
    const float* W1  = (const float*)d_in[2];
    const float* b1  = (const float*)d_in[3];
    const float* W2  = (const float*)d_in[4];
    const float* b2  = (const float*)d_in[5];

    float* out      = (float*)d_out;
    float* out_x    = out;
    float* out_pool = out + (size_t)Bn * Nn * Dn;
    float* out_adj  = out_pool + (size_t)Bn * Dn;

    __half *adjh, *xh, *nbh, *hh, *w1h, *w2h;
    float* gx;
    cudaGetSymbolAddress((void**)&adjh, g_adjh);
    cudaGetSymbolAddress((void**)&xh,   g_xh);
    cudaGetSymbolAddress((void**)&nbh,  g_nbh);
    cudaGetSymbolAddress((void**)&hh,   g_hh);
    cudaGetSymbolAddress((void**)&w1h,  g_w1h);
    cudaGetSymbolAddress((void**)&w2h,  g_w2h);
    cudaGetSymbolAddress((void**)&gx,   g_x);

    cudaFuncSetAttribute(mma_gemm<true,  false, false, false, false, true>,
        cudaFuncAttributeMaxDynamicSharedMemorySize, DSMEM_B);
    cudaFuncSetAttribute(mma_gemm<false, true,  true,  false, false, true>,
        cudaFuncAttributeMaxDynamicSharedMemorySize, DSMEM_B);
    cudaFuncSetAttribute(mma_gemm<false, true,  false, true,  true,  true>,
        cudaFuncAttributeMaxDynamicSharedMemorySize, DSMEM_B);
    cudaFuncSetAttribute(mma_gemm<false, true,  false, true,  true,  false>,
        cudaFuncAttributeMaxDynamicSharedMemorySize, DSMEM_B);

    softmax_rows<<<Nn, Nn>>>(adj, out_adj, adjh);
    cvt_weights<<<dim3(Ln * Hn * Dn / 4 / 256, 2), 256>>>(
        W1, W2, w1h, w2h, Ln * Hn * Dn / 4);
    cvt_fp16<<<((int)((size_t)Bn * Nn * Dn / 4) + 255) / 256, 256>>>(
        x0, xh, (int)((size_t)Bn * Nn * Dn / 4));

    const float* xin_f = x0;
    for (int i = 0; i < Ln; i++) {
        float* xout = (i == Ln - 1) ? out_x : gx;
        bool last = (i == Ln - 1);

        // neighbor = adj_norm @ x  (A = adj fp16; B = x fp16, T case) -> nb fp16
        mma_gemm<true, false, false, false, false, true>
            <<<dim3(Dn / 128, Nn / 128, Bn), 128, DSMEM_B>>>(
            adjh, xh, nullptr, nullptr, nullptr, nbh, Dn, Nn);

        // h = relu(nb @ W1^T + b1) -> h fp16
        mma_gemm<false, true, true, false, false, true>
            <<<dim3(Hn / 128, (Bn * Nn) / 128, 1), 128, DSMEM_B>>>(
            nbh, w1h + (size_t)i * Hn * Dn,
            b1 + (size_t)i * Hn, nullptr, nullptr, hh, Hn, Dn);

        // x = x + h @ W2^T + b2
        if (!last)
            mma_gemm<false, true, false, true, true, true>
                <<<dim3(Dn / 128, (Bn * Nn) / 128, 1), 128, DSMEM_B>>>(
                hh, w2h + (size_t)i * Dn * Hn,
                b2 + (size_t)i * Dn, xin_f, xout, xh, Dn, Hn);
        else
            mma_gemm<false, true, false, true, true, false>
                <<<dim3(Dn / 128, (Bn * Nn) / 128, 1), 128, DSMEM_B>>>(
                hh, w2h + (size_t)i * Dn * Hn,
                b2 + (size_t)i * Dn, xin_f, xout, nullptr, Dn, Hn);

        xin_f = xout;
    }

    pool_mean<<<(Bn * Dn) / 256, 256>>>(out_x, out_pool);
}